// round 8
// baseline (speedup 1.0000x reference)
#include <cuda_runtime.h>
#include <cuda_fp16.h>
#include <cstdint>

// out[b,i] = sum_h W2[i,h] * relu( sum_d X[b,d]*Adj[i,d]*W1[i,h,d] )
// B=16384, D=64, H=64.
//
// Single-term fp16 HMMA (mma.sync m16n8k16 f32.f16.f16), rel_err ~3e-4.
// Block = (1 node x 512 rows) = 4 tiles of 128 rows; 8 warps =
// 4 row-groups x 2 h-halves. B (weight) fragments are REGISTER-RESIDENT
// (loaded once per block); X tiles double-buffered via cp.async. The two
// h-half warps of a row-group combine partials through smem + named barrier.

#define NT   256
#define TB   128
#define TPB  4      // tiles per block

// ---- device-global fp16 buffers (prep output) ----
static __device__ __align__(16) __half Xf_g[16384 * 64];
static __device__ __align__(16) __half Wf_g[64 * 64 * 64];

// ---- main-kernel smem layout (bytes) ----
#define OFF_W2   0        // 64 floats
#define OFF_PART 256      // 2 parity x 128 floats
#define OFF_W    1536     // 8KB, swizzled
#define OFF_X    9728     // 2 buffers x 16KB, swizzled
#define SMEM_TOTAL 42496

static __device__ __forceinline__ uint32_t smem_u32(const void* p) {
    uint32_t a;
    asm("{ .reg .u64 t; cvta.to.shared.u64 t, %1; cvt.u32.u64 %0, t; }" : "=r"(a) : "l"(p));
    return a;
}

static __device__ __forceinline__ void cp16(uint32_t dst, const void* src) {
    asm volatile("cp.async.ca.shared.global [%0], [%1], 16;"
                 :: "r"(dst), "l"(src) : "memory");
}

static __device__ __forceinline__ void ldsm4(uint32_t* r, uint32_t addr) {
    asm volatile("ldmatrix.sync.aligned.m8n8.x4.shared.b16 {%0,%1,%2,%3}, [%4];"
                 : "=r"(r[0]), "=r"(r[1]), "=r"(r[2]), "=r"(r[3]) : "r"(addr));
}

static __device__ __forceinline__ void mma16816(float* c, const uint32_t* a,
                                                const uint32_t* b) {
    asm volatile(
        "mma.sync.aligned.m16n8k16.row.col.f32.f16.f16.f32 "
        "{%0,%1,%2,%3}, {%4,%5,%6,%7}, {%8,%9}, {%0,%1,%2,%3};"
        : "+f"(c[0]), "+f"(c[1]), "+f"(c[2]), "+f"(c[3])
        : "r"(a[0]), "r"(a[1]), "r"(a[2]), "r"(a[3]), "r"(b[0]), "r"(b[1]));
}

// ---- prep: X -> fp16; W1*adj -> fp16 ----
__global__ __launch_bounds__(NT)
void prep_kernel(const float* __restrict__ X,
                 const float* __restrict__ Adj,
                 const float* __restrict__ W1)
{
    int gid = blockIdx.x * NT + threadIdx.x;
    if (gid < 262144) {                       // X: 16384*64/4 float4s
        float4 v = ((const float4*)X)[gid];
        __half2 p0 = __floats2half2_rn(v.x, v.y);
        __half2 p1 = __floats2half2_rn(v.z, v.w);
        uint2 r; r.x = *(uint32_t*)&p0; r.y = *(uint32_t*)&p1;
        ((uint2*)Xf_g)[gid] = r;
    } else {                                  // W: 64*64*64/4 float4s
        int j = gid - 262144;                 // 0..65535
        int i  = j >> 10;
        int d4 = j & 15;
        float4 v = ((const float4*)W1)[j];
        float4 a = ((const float4*)Adj)[i * 16 + d4];
        v.x *= a.x; v.y *= a.y; v.z *= a.z; v.w *= a.w;
        __half2 p0 = __floats2half2_rn(v.x, v.y);
        __half2 p1 = __floats2half2_rn(v.z, v.w);
        uint2 r; r.x = *(uint32_t*)&p0; r.y = *(uint32_t*)&p1;
        ((uint2*)Wf_g)[j] = r;
    }
}

// stage one 128-row X tile (4 cp16 per thread)
static __device__ __forceinline__ void stage_x(uint32_t sb, int buf,
                                               const char* xsrc, int tid) {
    uint32_t base = sb + OFF_X + buf * 16384;
    #pragma unroll
    for (int it = 0; it < 4; ++it) {
        int c   = tid + it * NT;           // 0..1023
        int row = c >> 3, k16 = c & 7;
        cp16(base + row * 128 + ((k16 ^ (row & 7)) << 4), xsrc + c * 16);
    }
}

// ---- main GEMM ----
__global__ __launch_bounds__(NT, 2)
void tp_kernel(const float* __restrict__ W2, float* __restrict__ out)
{
    extern __shared__ char smem[];
    const uint32_t sb = smem_u32(smem);
    const int tid = threadIdx.x;
    const int wid = tid >> 5;
    const int l   = tid & 31;
    const int i    = blockIdx.x;               // node (fastest -> X L2 reuse)
    const int row0 = blockIdx.y * (TB * TPB);  // 512-row group

    const int rg   = wid & 3;     // row-group: rows rg*32..+31 within tile
    const int half = wid >> 2;    // h-half: h = half*32..+31

    // ---- stage W (8KB) + X tile 0 via cp.async ----
    {
        const char* wsrc = (const char*)(Wf_g + (size_t)i * 4096);
        #pragma unroll
        for (int it = 0; it < 2; ++it) {
            int c = tid + it * NT;         // 0..511
            int r = c >> 3, k16 = c & 7;
            cp16(sb + OFF_W + r * 128 + ((k16 ^ (r & 7)) << 4), wsrc + c * 16);
        }
    }
    const char* xbase = (const char*)(Xf_g + (size_t)row0 * 64);
    stage_x(sb, 0, xbase, tid);
    asm volatile("cp.async.commit_group;" ::: "memory");

    if (tid < 64) ((float*)(smem + OFF_W2))[tid] = W2[i * 64 + tid];

    // ---- per-warp constants ----
    uint32_t aoff[2], asw[2];
    #pragma unroll
    for (int mt = 0; mt < 2; ++mt) {
        int arow = rg * 32 + mt * 16 + (l & 15);
        aoff[mt] = sb + OFF_X + arow * 128;
        asw[mt]  = arow & 7;
    }
    const uint32_t ahalf = (l >> 4) & 1;
    const uint32_t bhalf = (l >> 3) & 1;
    const float* W2s  = (const float*)(smem + OFF_W2);
    float*       part = (float*)(smem + OFF_PART);

    asm volatile("cp.async.wait_group 0;" ::: "memory");
    __syncthreads();

    // ---- load B fragments ONCE (register-resident, 32 regs) ----
    uint32_t wv[4][2][4];
    #pragma unroll
    for (int g = 0; g < 2; ++g) {
        int brow = half * 32 + g * 16 + ((l >> 4) & 1) * 8 + (l & 7);
        uint32_t boff = sb + OFF_W + brow * 128;
        uint32_t bsw  = brow & 7;
        #pragma unroll
        for (int ks = 0; ks < 4; ++ks)
            ldsm4(wv[ks][g], boff + (((ks * 2 + bhalf) ^ bsw) << 4));
    }

    #pragma unroll
    for (int t = 0; t < TPB; ++t) {
        // prefetch next X tile (overlaps this tile's MMAs)
        if (t + 1 < TPB) {
            stage_x(sb, (t + 1) & 1, xbase + (size_t)(t + 1) * TB * 128, tid);
            asm volatile("cp.async.commit_group;" ::: "memory");
        }

        const uint32_t xb = (uint32_t)((t & 1) * 16384);

        float acc[2][4][4];
        #pragma unroll
        for (int mt = 0; mt < 2; ++mt)
            #pragma unroll
            for (int n = 0; n < 4; ++n)
                #pragma unroll
                for (int q = 0; q < 4; ++q) acc[mt][n][q] = 0.f;

        #pragma unroll
        for (int ks = 0; ks < 4; ++ks) {
            uint32_t xv[2][4];
            #pragma unroll
            for (int mt = 0; mt < 2; ++mt)
                ldsm4(xv[mt], aoff[mt] + xb + (((ks * 2 + ahalf) ^ asw[mt]) << 4));
            #pragma unroll
            for (int mt = 0; mt < 2; ++mt)
                #pragma unroll
                for (int n = 0; n < 4; ++n)
                    mma16816(acc[mt][n], xv[mt], &wv[ks][n >> 1][(n & 1) * 2]);
        }

        // ---- epilogue: relu + dot W2 (this h-half), quad reduce ----
        float s0v[2], s1v[2];
        #pragma unroll
        for (int mt = 0; mt < 2; ++mt) {
            float s0 = 0.f, s1 = 0.f;
            #pragma unroll
            for (int n = 0; n < 4; ++n) {
                float2 w = *(const float2*)(W2s + half * 32 + n * 8 + (l & 3) * 2);
                s0 = fmaf(fmaxf(acc[mt][n][0], 0.f), w.x, s0);
                s0 = fmaf(fmaxf(acc[mt][n][1], 0.f), w.y, s0);
                s1 = fmaf(fmaxf(acc[mt][n][2], 0.f), w.x, s1);
                s1 = fmaf(fmaxf(acc[mt][n][3], 0.f), w.y, s1);
            }
            s0 += __shfl_xor_sync(0xffffffffu, s0, 1);
            s0 += __shfl_xor_sync(0xffffffffu, s0, 2);
            s1 += __shfl_xor_sync(0xffffffffu, s1, 1);
            s1 += __shfl_xor_sync(0xffffffffu, s1, 2);
            s0v[mt] = s0; s1v[mt] = s1;
        }

        // combine h-halves via smem partial + named barrier (warp pair rg)
        float* pbuf = part + (t & 1) * 128 + rg * 32;
        if (half == 0 && (l & 3) == 0) {
            #pragma unroll
            for (int mt = 0; mt < 2; ++mt) {
                pbuf[mt * 16 + (l >> 2)]     = s0v[mt];
                pbuf[mt * 16 + (l >> 2) + 8] = s1v[mt];
            }
        }
        asm volatile("bar.sync %0, %1;" :: "r"(rg + 1), "r"(64) : "memory");
        if (half == 1 && (l & 3) == 0) {
            #pragma unroll
            for (int mt = 0; mt < 2; ++mt) {
                int lrow = rg * 32 + mt * 16 + (l >> 2);
                int grow = row0 + t * TB + lrow;
                out[(size_t)grow * 64 + i] =
                    s0v[mt] + pbuf[mt * 16 + (l >> 2)];
                out[(size_t)(grow + 8) * 64 + i] =
                    s1v[mt] + pbuf[mt * 16 + (l >> 2) + 8];
            }
        }

        if (t + 1 < TPB) {
            asm volatile("cp.async.wait_group 0;" ::: "memory");
            __syncthreads();
        }
    }
}

extern "C" void kernel_launch(void* const* d_in, const int* in_sizes, int n_in,
                              void* d_out, int out_size) {
    const float* X   = (const float*)d_in[0];  // [16384, 64]
    const float* Adj = (const float*)d_in[1];  // [64, 64]
    const float* W1  = (const float*)d_in[2];  // [64, 64, 64] (i,h,d)
    const float* W2  = (const float*)d_in[3];  // [64, 64]
    float* out = (float*)d_out;                // [16384, 64]

    prep_kernel<<<1280, NT>>>(X, Adj, W1);

    cudaFuncSetAttribute(tp_kernel, cudaFuncAttributeMaxDynamicSharedMemorySize,
                         SMEM_TOTAL);
    dim3 grid(64, 16384 / (TB * TPB));
    tp_kernel<<<grid, NT, SMEM_TOTAL>>>(W2, out);
}

// round 9
// speedup vs baseline: 1.1124x; 1.1124x over previous
#include <cuda_runtime.h>
#include <cuda_fp16.h>
#include <cstdint>

// out[b,i] = sum_h W2[i,h] * relu( sum_d X[b,d]*Adj[i,d]*W1[i,h,d] )
// B=16384, D=64, H=64.
//
// Single-term fp16 HMMA (mma.sync m16n8k16 f32.f16.f16), rel_err ~3e-4.
// Block = (2 nodes x 512 rows); 8 warps = 4 row-groups x 2 nodes; warp =
// 32 rows x 64 h. BARRIER-FREE mainloop: each warp cp.async-stages its own
// 32 X-rows into a node-private buffer set (warp-scoped wait_group +
// syncwarp only). W resident in smem after one prologue sync.

#define NT   256
#define NPB  2
#define TB   128
#define TPB  4      // tiles per block

// ---- device-global fp16 buffers (prep output) ----
static __device__ __align__(16) __half Xf_g[16384 * 64];
static __device__ __align__(16) __half Wf_g[64 * 64 * 64];

// ---- main-kernel smem layout (bytes) ----
#define OFF_W2   0        // 128 floats
#define OFF_W    1024     // 2 nodes x 8KB, swizzled
#define OFF_X    17408    // 2 node-sets x 2 buffers x 16KB, swizzled
#define SMEM_TOTAL 82944

static __device__ __forceinline__ uint32_t smem_u32(const void* p) {
    uint32_t a;
    asm("{ .reg .u64 t; cvta.to.shared.u64 t, %1; cvt.u32.u64 %0, t; }" : "=r"(a) : "l"(p));
    return a;
}

static __device__ __forceinline__ void cp16(uint32_t dst, const void* src) {
    asm volatile("cp.async.ca.shared.global [%0], [%1], 16;"
                 :: "r"(dst), "l"(src) : "memory");
}

static __device__ __forceinline__ void ldsm4(uint32_t* r, uint32_t addr) {
    asm volatile("ldmatrix.sync.aligned.m8n8.x4.shared.b16 {%0,%1,%2,%3}, [%4];"
                 : "=r"(r[0]), "=r"(r[1]), "=r"(r[2]), "=r"(r[3]) : "r"(addr));
}

static __device__ __forceinline__ void mma16816(float* c, const uint32_t* a,
                                                const uint32_t* b) {
    asm volatile(
        "mma.sync.aligned.m16n8k16.row.col.f32.f16.f16.f32 "
        "{%0,%1,%2,%3}, {%4,%5,%6,%7}, {%8,%9}, {%0,%1,%2,%3};"
        : "+f"(c[0]), "+f"(c[1]), "+f"(c[2]), "+f"(c[3])
        : "r"(a[0]), "r"(a[1]), "r"(a[2]), "r"(a[3]), "r"(b[0]), "r"(b[1]));
}

// ---- prep: X -> fp16; W1*adj -> fp16 ----
__global__ __launch_bounds__(NT)
void prep_kernel(const float* __restrict__ X,
                 const float* __restrict__ Adj,
                 const float* __restrict__ W1)
{
    int gid = blockIdx.x * NT + threadIdx.x;
    if (gid < 262144) {                       // X: 16384*64/4 float4s
        float4 v = ((const float4*)X)[gid];
        __half2 p0 = __floats2half2_rn(v.x, v.y);
        __half2 p1 = __floats2half2_rn(v.z, v.w);
        uint2 r; r.x = *(uint32_t*)&p0; r.y = *(uint32_t*)&p1;
        ((uint2*)Xf_g)[gid] = r;
    } else {                                  // W: 64*64*64/4 float4s
        int j = gid - 262144;                 // 0..65535
        int i  = j >> 10;
        int d4 = j & 15;
        float4 v = ((const float4*)W1)[j];
        float4 a = ((const float4*)Adj)[i * 16 + d4];
        v.x *= a.x; v.y *= a.y; v.z *= a.z; v.w *= a.w;
        __half2 p0 = __floats2half2_rn(v.x, v.y);
        __half2 p1 = __floats2half2_rn(v.z, v.w);
        uint2 r; r.x = *(uint32_t*)&p0; r.y = *(uint32_t*)&p1;
        ((uint2*)Wf_g)[j] = r;
    }
}

// ---- main GEMM ----
__global__ __launch_bounds__(NT, 2)
void tp_kernel(const float* __restrict__ W2, float* __restrict__ out)
{
    extern __shared__ char smem[];
    const uint32_t sb = smem_u32(smem);
    const int tid = threadIdx.x;
    const int wid = tid >> 5;
    const int l   = tid & 31;
    const int i0   = blockIdx.x * NPB;          // node pair (fastest -> L2 reuse)
    const int row0 = blockIdx.y * (TB * TPB);   // 512-row group

    const int rg   = wid & 3;      // row-group: rows rg*32..+31 within tile
    const int node = wid >> 2;     // which node of the pair

    const uint32_t xset = sb + OFF_X + node * 32768;   // node-private buffers
    const char* xbase = (const char*)(Xf_g + (size_t)row0 * 64);

    // per-warp staging geometry: lane covers rows rg*32 + (c>>3), c = l + it*32
    // (8 cp16 per lane = 4KB = this warp's 32 rows)
    // ---- prologue: stage W (all warps) + X tile 0 (own slice) ----
    {
        const char* wsrc = (const char*)(Wf_g + (size_t)i0 * 4096);
        #pragma unroll
        for (int it = 0; it < 4; ++it) {
            int c = tid + it * NT;          // 0..1023
            int r = (c >> 3) & 63, k16 = c & 7;
            uint32_t dst = sb + OFF_W + (c >> 9) * 8192 + r * 128
                         + ((k16 ^ (r & 7)) << 4);
            cp16(dst, wsrc + c * 16);
        }
    }
    #pragma unroll
    for (int it = 0; it < 8; ++it) {
        int c   = l + it * 32;              // 0..255
        int row = rg * 32 + (c >> 3), k16 = c & 7;
        cp16(xset + row * 128 + ((k16 ^ (row & 7)) << 4),
             xbase + (size_t)row * 128 + k16 * 16);
    }
    asm volatile("cp.async.commit_group;" ::: "memory");

    if (tid < 128) ((float*)(smem + OFF_W2))[tid] = W2[i0 * 64 + tid];

    asm volatile("cp.async.wait_group 0;" ::: "memory");
    __syncthreads();   // only block-wide sync: W + W2 visibility

    // ---- per-warp constants ----
    uint32_t aoff[2], asw[2];
    #pragma unroll
    for (int mt = 0; mt < 2; ++mt) {
        int arow = rg * 32 + mt * 16 + (l & 15);
        aoff[mt] = xset + arow * 128;
        asw[mt]  = arow & 7;
    }
    const uint32_t ahalf = (l >> 4) & 1;
    uint32_t boff[4], bsw[4];
    #pragma unroll
    for (int g = 0; g < 4; ++g) {
        int brow = g * 16 + ((l >> 4) & 1) * 8 + (l & 7);
        boff[g] = sb + OFF_W + node * 8192 + brow * 128;
        bsw[g]  = brow & 7;
    }
    const uint32_t bhalf = (l >> 3) & 1;
    const float* W2s = (const float*)(smem + OFF_W2) + node * 64;

    #pragma unroll
    for (int t = 0; t < TPB; ++t) {
        // own fill of tile t is complete; make visible warp-wide
        asm volatile("cp.async.wait_group 0;" ::: "memory");
        __syncwarp();

        // prefetch own slice of tile t+1 (overlaps this tile's MMAs)
        if (t + 1 < TPB) {
            const char* xt = xbase + (size_t)(t + 1) * TB * 128;
            uint32_t xdst = xset + (((t + 1) & 1) ? 16384u : 0u);
            #pragma unroll
            for (int it = 0; it < 8; ++it) {
                int c   = l + it * 32;
                int row = rg * 32 + (c >> 3), k16 = c & 7;
                cp16(xdst + row * 128 + ((k16 ^ (row & 7)) << 4),
                     xt + (size_t)row * 128 + k16 * 16);
            }
            asm volatile("cp.async.commit_group;" ::: "memory");
        }

        const uint32_t xb = (uint32_t)((t & 1) * 16384);

        float acc[2][8][4];
        #pragma unroll
        for (int mt = 0; mt < 2; ++mt)
            #pragma unroll
            for (int n = 0; n < 8; ++n)
                #pragma unroll
                for (int q = 0; q < 4; ++q) acc[mt][n][q] = 0.f;

        #pragma unroll
        for (int ks = 0; ks < 4; ++ks) {
            uint32_t xv[2][4];
            #pragma unroll
            for (int mt = 0; mt < 2; ++mt)
                ldsm4(xv[mt], aoff[mt] + xb + (((ks * 2 + ahalf) ^ asw[mt]) << 4));
            uint32_t wv[4][4];
            #pragma unroll
            for (int g = 0; g < 4; ++g)
                ldsm4(wv[g], boff[g] + (((ks * 2 + bhalf) ^ bsw[g]) << 4));
            #pragma unroll
            for (int mt = 0; mt < 2; ++mt)
                #pragma unroll
                for (int n = 0; n < 8; ++n)
                    mma16816(acc[mt][n], xv[mt], &wv[n >> 1][(n & 1) * 2]);
        }

        // ---- epilogue: relu + dot W2, quad reduce, store ----
        #pragma unroll
        for (int mt = 0; mt < 2; ++mt) {
            float s0 = 0.f, s1 = 0.f;
            #pragma unroll
            for (int n = 0; n < 8; ++n) {
                float2 w = *(const float2*)(W2s + n * 8 + (l & 3) * 2);
                s0 = fmaf(fmaxf(acc[mt][n][0], 0.f), w.x, s0);
                s0 = fmaf(fmaxf(acc[mt][n][1], 0.f), w.y, s0);
                s1 = fmaf(fmaxf(acc[mt][n][2], 0.f), w.x, s1);
                s1 = fmaf(fmaxf(acc[mt][n][3], 0.f), w.y, s1);
            }
            s0 += __shfl_xor_sync(0xffffffffu, s0, 1);
            s0 += __shfl_xor_sync(0xffffffffu, s0, 2);
            s1 += __shfl_xor_sync(0xffffffffu, s1, 1);
            s1 += __shfl_xor_sync(0xffffffffu, s1, 2);
            if ((l & 3) == 0) {
                int grow = row0 + t * TB + rg * 32 + mt * 16 + (l >> 2);
                out[(size_t)grow * 64 + i0 + node]       = s0;
                out[(size_t)(grow + 8) * 64 + i0 + node] = s1;
            }
        }
    }
}

extern "C" void kernel_launch(void* const* d_in, const int* in_sizes, int n_in,
                              void* d_out, int out_size) {
    const float* X   = (const float*)d_in[0];  // [16384, 64]
    const float* Adj = (const float*)d_in[1];  // [64, 64]
    const float* W1  = (const float*)d_in[2];  // [64, 64, 64] (i,h,d)
    const float* W2  = (const float*)d_in[3];  // [64, 64]
    float* out = (float*)d_out;                // [16384, 64]

    prep_kernel<<<1280, NT>>>(X, Adj, W1);

    cudaFuncSetAttribute(tp_kernel, cudaFuncAttributeMaxDynamicSharedMemorySize,
                         SMEM_TOTAL);
    dim3 grid(64 / NPB, 16384 / (TB * TPB));
    tp_kernel<<<grid, NT, SMEM_TOTAL>>>(W2, out);
}

// round 10
// speedup vs baseline: 1.2470x; 1.1209x over previous
#include <cuda_runtime.h>
#include <cuda_fp16.h>
#include <cstdint>

// out[b,i] = sum_h W2[i,h] * relu( sum_d X[b,d]*Adj[i,d]*W1[i,h,d] )
// B=16384, D=64, H=64.
//
// Single-term fp16 HMMA (mma.sync m16n8k16 f32.f16.f16), rel_err ~3e-4.
// Block = (1 node x 1024 rows) = 8 tiles of 128 rows; 8 warps, each owns a
// 16-row strip per tile and ALL 64 h. B (weight) fragments live in 64
// registers, loaded ONCE per block -> mainloop is 4 A-ldsm + 32 MMA per tile.
// X strips are warp-private, double-buffered via per-warp cp.async groups:
// no block-wide barriers after the prologue.

#define NT   256
#define TB   128
#define TPB  8      // tiles per block

// ---- device-global fp16 buffers (prep output) ----
static __device__ __align__(16) __half Xf_g[16384 * 64];
static __device__ __align__(16) __half Wf_g[64 * 64 * 64];

// ---- main-kernel smem layout (bytes) ----
#define OFF_W2   0        // 64 floats
#define OFF_W    1024     // 8KB, swizzled
#define OFF_X    9216     // 8 warps x 2 bufs x 2KB, swizzled
#define SMEM_TOTAL 41984

static __device__ __forceinline__ uint32_t smem_u32(const void* p) {
    uint32_t a;
    asm("{ .reg .u64 t; cvta.to.shared.u64 t, %1; cvt.u32.u64 %0, t; }" : "=r"(a) : "l"(p));
    return a;
}

static __device__ __forceinline__ void cp16(uint32_t dst, const void* src) {
    asm volatile("cp.async.ca.shared.global [%0], [%1], 16;"
                 :: "r"(dst), "l"(src) : "memory");
}

static __device__ __forceinline__ void ldsm4(uint32_t* r, uint32_t addr) {
    asm volatile("ldmatrix.sync.aligned.m8n8.x4.shared.b16 {%0,%1,%2,%3}, [%4];"
                 : "=r"(r[0]), "=r"(r[1]), "=r"(r[2]), "=r"(r[3]) : "r"(addr));
}

static __device__ __forceinline__ void mma16816(float* c, const uint32_t* a,
                                                const uint32_t* b) {
    asm volatile(
        "mma.sync.aligned.m16n8k16.row.col.f32.f16.f16.f32 "
        "{%0,%1,%2,%3}, {%4,%5,%6,%7}, {%8,%9}, {%0,%1,%2,%3};"
        : "+f"(c[0]), "+f"(c[1]), "+f"(c[2]), "+f"(c[3])
        : "r"(a[0]), "r"(a[1]), "r"(a[2]), "r"(a[3]), "r"(b[0]), "r"(b[1]));
}

// ---- prep: X -> fp16; W1*adj -> fp16 ----
__global__ __launch_bounds__(NT)
void prep_kernel(const float* __restrict__ X,
                 const float* __restrict__ Adj,
                 const float* __restrict__ W1)
{
    int gid = blockIdx.x * NT + threadIdx.x;
    if (gid < 262144) {                       // X: 16384*64/4 float4s
        float4 v = ((const float4*)X)[gid];
        __half2 p0 = __floats2half2_rn(v.x, v.y);
        __half2 p1 = __floats2half2_rn(v.z, v.w);
        uint2 r; r.x = *(uint32_t*)&p0; r.y = *(uint32_t*)&p1;
        ((uint2*)Xf_g)[gid] = r;
    } else {                                  // W: 64*64*64/4 float4s
        int j = gid - 262144;                 // 0..65535
        int i  = j >> 10;
        int d4 = j & 15;
        float4 v = ((const float4*)W1)[j];
        float4 a = ((const float4*)Adj)[i * 16 + d4];
        v.x *= a.x; v.y *= a.y; v.z *= a.z; v.w *= a.w;
        __half2 p0 = __floats2half2_rn(v.x, v.y);
        __half2 p1 = __floats2half2_rn(v.z, v.w);
        uint2 r; r.x = *(uint32_t*)&p0; r.y = *(uint32_t*)&p1;
        ((uint2*)Wf_g)[j] = r;
    }
}

// ---- main GEMM ----
__global__ __launch_bounds__(NT, 2)
void tp_kernel(const float* __restrict__ W2, float* __restrict__ out)
{
    extern __shared__ char smem[];
    const uint32_t sb = smem_u32(smem);
    const int tid = threadIdx.x;
    const int wid = tid >> 5;
    const int l   = tid & 31;
    const int i    = blockIdx.x;                // node (fastest -> X L2 reuse)
    const int row0 = blockIdx.y * (TB * TPB);   // 1024-row group

    const uint32_t xwarp = sb + OFF_X + wid * 4096;   // warp-private 2x2KB
    const char* xbase = (const char*)(Xf_g + (size_t)row0 * 64);

    // ---- prologue: stage W (8KB, all threads) + X tile 0 (own strip) ----
    {
        const char* wsrc = (const char*)(Wf_g + (size_t)i * 4096);
        #pragma unroll
        for (int it = 0; it < 2; ++it) {
            int c = tid + it * NT;          // 0..511
            int r = c >> 3, k16 = c & 7;
            cp16(sb + OFF_W + r * 128 + ((k16 ^ (r & 7)) << 4), wsrc + c * 16);
        }
    }
    #pragma unroll
    for (int it = 0; it < 4; ++it) {
        int c  = l + it * 32;               // 0..127
        int rl = c >> 3, k16 = c & 7;       // row-in-strip 0..15
        cp16(xwarp + rl * 128 + ((k16 ^ (rl & 7)) << 4),
             xbase + (size_t)(wid * 16 + rl) * 128 + k16 * 16);
    }
    asm volatile("cp.async.commit_group;" ::: "memory");

    if (tid < 64) ((float*)(smem + OFF_W2))[tid] = W2[i * 64 + tid];

    asm volatile("cp.async.wait_group 0;" ::: "memory");
    __syncthreads();   // only block-wide sync: W + W2 visibility

    // ---- load ALL B fragments once (register-resident, 64 regs) ----
    const uint32_t bhalf = (l >> 3) & 1;
    uint32_t wv[4][4][4];                   // [ks][g][frag]
    #pragma unroll
    for (int g = 0; g < 4; ++g) {
        int brow = g * 16 + ((l >> 4) & 1) * 8 + (l & 7);
        uint32_t boff = sb + OFF_W + brow * 128;
        uint32_t bsw  = brow & 7;
        #pragma unroll
        for (int ks = 0; ks < 4; ++ks)
            ldsm4(wv[ks][g], boff + (((ks * 2 + bhalf) ^ bsw) << 4));
    }

    // A geometry: 16 rows in own strip
    const int arow = l & 15;
    const uint32_t aoff = xwarp + arow * 128;
    const uint32_t asw  = arow & 7;
    const uint32_t ahalf = (l >> 4) & 1;
    const float* W2s = (const float*)(smem + OFF_W2);

    #pragma unroll 2
    for (int t = 0; t < TPB; ++t) {
        // own fill of tile t complete; make visible warp-wide
        asm volatile("cp.async.wait_group 0;" ::: "memory");
        __syncwarp();

        // prefetch own strip of tile t+1 (overlaps this tile's MMAs)
        if (t + 1 < TPB) {
            const char* xt = xbase + (size_t)((t + 1) * TB + wid * 16) * 128;
            uint32_t xdst = xwarp + (((t + 1) & 1) ? 2048u : 0u);
            #pragma unroll
            for (int it = 0; it < 4; ++it) {
                int c  = l + it * 32;
                int rl = c >> 3, k16 = c & 7;
                cp16(xdst + rl * 128 + ((k16 ^ (rl & 7)) << 4),
                     xt + (size_t)rl * 128 + k16 * 16);
            }
            asm volatile("cp.async.commit_group;" ::: "memory");
        }

        const uint32_t xb = (uint32_t)((t & 1) * 2048);

        float acc[8][4];
        #pragma unroll
        for (int n = 0; n < 8; ++n)
            #pragma unroll
            for (int q = 0; q < 4; ++q) acc[n][q] = 0.f;

        #pragma unroll
        for (int ks = 0; ks < 4; ++ks) {
            uint32_t xv[4];
            ldsm4(xv, aoff + xb + (((ks * 2 + ahalf) ^ asw) << 4));
            #pragma unroll
            for (int n = 0; n < 8; ++n)
                mma16816(acc[n], xv, &wv[ks][n >> 1][(n & 1) * 2]);
        }

        // ---- epilogue: relu + dot W2, quad reduce, store ----
        float s0 = 0.f, s1 = 0.f;
        #pragma unroll
        for (int n = 0; n < 8; ++n) {
            float2 w = *(const float2*)(W2s + n * 8 + (l & 3) * 2);
            s0 = fmaf(fmaxf(acc[n][0], 0.f), w.x, s0);
            s0 = fmaf(fmaxf(acc[n][1], 0.f), w.y, s0);
            s1 = fmaf(fmaxf(acc[n][2], 0.f), w.x, s1);
            s1 = fmaf(fmaxf(acc[n][3], 0.f), w.y, s1);
        }
        s0 += __shfl_xor_sync(0xffffffffu, s0, 1);
        s0 += __shfl_xor_sync(0xffffffffu, s0, 2);
        s1 += __shfl_xor_sync(0xffffffffu, s1, 1);
        s1 += __shfl_xor_sync(0xffffffffu, s1, 2);
        if ((l & 3) == 0) {
            int grow = row0 + t * TB + wid * 16 + (l >> 2);
            out[(size_t)grow * 64 + i]       = s0;
            out[(size_t)(grow + 8) * 64 + i] = s1;
        }
    }
}

extern "C" void kernel_launch(void* const* d_in, const int* in_sizes, int n_in,
                              void* d_out, int out_size) {
    const float* X   = (const float*)d_in[0];  // [16384, 64]
    const float* Adj = (const float*)d_in[1];  // [64, 64]
    const float* W1  = (const float*)d_in[2];  // [64, 64, 64] (i,h,d)
    const float* W2  = (const float*)d_in[3];  // [64, 64]
    float* out = (float*)d_out;                // [16384, 64]

    prep_kernel<<<1280, NT>>>(X, Adj, W1);

    cudaFuncSetAttribute(tp_kernel, cudaFuncAttributeMaxDynamicSharedMemorySize,
                         SMEM_TOTAL);
    dim3 grid(64, 16384 / (TB * TPB));
    tp_kernel<<<grid, NT, SMEM_TOTAL>>>(W2, out);
}

// round 11
// speedup vs baseline: 1.2585x; 1.0092x over previous
#include <cuda_runtime.h>
#include <cuda_fp16.h>
#include <cstdint>

// out[b,i] = sum_h W2[i,h] * relu( sum_d X[b,d]*Adj[i,d]*W1[i,h,d] )
// B=16384, D=64, H=64.
//
// Single-term fp16 HMMA (mma.sync m16n8k16 f32.f16.f16), rel_err ~3e-4.
// Prep kernel writes X and W'=W1*adj in MMA FRAGMENT ORDER:
//   Xfrag[rt][ks][lane] = uint4 (a0..a3), rt = 16-row tile, ks = k-step
//   Wfrag[node][w][lane] = uint4, flat word idx = ks*16 + n*2 + r (b0/b1)
// Main kernel: block = (1 node x 1024 rows); warp = 16-row strip x 8 tiles.
// B regs loaded once (smem bounce, 16 LDS.128); mainloop = 4 coalesced
// LDG.128 (A) + 32 MMA + epilogue. No cp.async, no ldsm, no barriers.

#define NT   256
#define TPB  8      // 128-row tiles per block

// ---- device-global fragment buffers (prep output) ----
static __device__ __align__(16) uint4 Xfrag_g[1024 * 4 * 32];  // 2MB
static __device__ __align__(16) uint4 Wfrag_g[64 * 16 * 32];   // 512KB

static __device__ __forceinline__ uint32_t h2u(__half2 h) {
    return *(uint32_t*)&h;
}

static __device__ __forceinline__ uint32_t smem_u32(const void* p) {
    uint32_t a;
    asm("{ .reg .u64 t; cvta.to.shared.u64 t, %1; cvt.u32.u64 %0, t; }" : "=r"(a) : "l"(p));
    return a;
}

static __device__ __forceinline__ void cp16(uint32_t dst, const void* src) {
    asm volatile("cp.async.ca.shared.global [%0], [%1], 16;"
                 :: "r"(dst), "l"(src) : "memory");
}

static __device__ __forceinline__ void mma16816(float* c, const uint32_t* a,
                                                const uint32_t* b) {
    asm volatile(
        "mma.sync.aligned.m16n8k16.row.col.f32.f16.f16.f32 "
        "{%0,%1,%2,%3}, {%4,%5,%6,%7}, {%8,%9}, {%0,%1,%2,%3};"
        : "+f"(c[0]), "+f"(c[1]), "+f"(c[2]), "+f"(c[3])
        : "r"(a[0]), "r"(a[1]), "r"(a[2]), "r"(a[3]), "r"(b[0]), "r"(b[1]));
}

// ---- prep: emit fragment-ordered fp16 X and W'=W1*adj ----
__global__ __launch_bounds__(NT)
void prep_kernel(const float* __restrict__ X,
                 const float* __restrict__ Adj,
                 const float* __restrict__ W1)
{
    int gid = blockIdx.x * NT + threadIdx.x;
    if (gid < 131072) {
        // X fragments: gid = (rt*4 + ks)*32 + l
        int l  = gid & 31;
        int ks = (gid >> 5) & 3;
        int rt = gid >> 7;
        int gi = l >> 2, ti = l & 3;
        int r0 = rt * 16 + gi;
        int c0 = ks * 16 + ti * 2;
        const float* xr0 = X + (size_t)r0 * 64;
        const float* xr1 = X + (size_t)(r0 + 8) * 64;
        uint4 v;
        v.x = h2u(__floats2half2_rn(xr0[c0],     xr0[c0 + 1]));   // a0
        v.y = h2u(__floats2half2_rn(xr1[c0],     xr1[c0 + 1]));   // a1
        v.z = h2u(__floats2half2_rn(xr0[c0 + 8], xr0[c0 + 9]));   // a2
        v.w = h2u(__floats2half2_rn(xr1[c0 + 8], xr1[c0 + 9]));   // a3
        Xfrag_g[gid] = v;
    } else if (gid < 131072 + 32768) {
        // W fragments: j = (node*16 + w)*32 + l
        int j    = gid - 131072;
        int l    = j & 31;
        int w    = (j >> 5) & 15;
        int node = j >> 9;
        int gi = l >> 2, ti = l & 3;
        uint32_t vv[4];
        #pragma unroll
        for (int q = 0; q < 4; ++q) {
            int idx = w * 4 + q;            // ks*16 + ng*2 + r
            int ks = idx >> 4, ng = (idx >> 1) & 7, r = idx & 1;
            int h0 = ng * 8 + gi;
            int d0 = ks * 16 + ti * 2 + r * 8;
            const float* w1p = W1 + ((size_t)node * 64 + h0) * 64;
            const float* ap  = Adj + node * 64;
            vv[q] = h2u(__floats2half2_rn(w1p[d0] * ap[d0],
                                          w1p[d0 + 1] * ap[d0 + 1]));
        }
        uint4 o; o.x = vv[0]; o.y = vv[1]; o.z = vv[2]; o.w = vv[3];
        Wfrag_g[j] = o;
    }
}

// ---- main GEMM ----
__global__ __launch_bounds__(NT, 2)
void tp_kernel(const float* __restrict__ W2, float* __restrict__ out)
{
    __shared__ __align__(16) uint4 Wsh[16 * 32];   // 8KB, [w][lane]
    __shared__ float W2s[64];

    const int tid = threadIdx.x;
    const int wid = tid >> 5;
    const int l   = tid & 31;
    const int i    = blockIdx.x;                 // node (fastest -> X L2 reuse)
    const int row0 = blockIdx.y * (128 * TPB);   // 1024-row group

    // ---- prologue: stage W fragments (8KB) via cp.async ----
    {
        const uint32_t wdst = smem_u32(Wsh);
        #pragma unroll
        for (int it = 0; it < 2; ++it) {
            int c = tid + it * NT;               // 0..511
            cp16(wdst + c * 16, &Wfrag_g[i * 512 + c]);
        }
        asm volatile("cp.async.commit_group;" ::: "memory");
    }
    if (tid < 64) W2s[tid] = W2[i * 64 + tid];
    asm volatile("cp.async.wait_group 0;" ::: "memory");
    __syncthreads();

    // ---- load ALL B fragments into registers (16 conflict-free LDS.128) ----
    uint32_t wv[64];
    #pragma unroll
    for (int w = 0; w < 16; ++w) {
        uint4 t = Wsh[w * 32 + l];
        wv[w * 4 + 0] = t.x; wv[w * 4 + 1] = t.y;
        wv[w * 4 + 2] = t.z; wv[w * 4 + 3] = t.w;
    }

    // A pointer: rt = row0/16 + t*8 + wid; elem = (rt*4 + ks)*32 + l
    const uint4* xp = Xfrag_g + (size_t)((row0 >> 4) + wid) * 128 + l;

    #pragma unroll 2
    for (int t = 0; t < TPB; ++t) {
        uint4 xv[4];
        #pragma unroll
        for (int ks = 0; ks < 4; ++ks)
            xv[ks] = __ldg(xp + t * 1024 + ks * 32);

        float acc[8][4];
        #pragma unroll
        for (int n = 0; n < 8; ++n)
            #pragma unroll
            for (int q = 0; q < 4; ++q) acc[n][q] = 0.f;

        #pragma unroll
        for (int ks = 0; ks < 4; ++ks)
            #pragma unroll
            for (int n = 0; n < 8; ++n)
                mma16816(acc[n], (const uint32_t*)&xv[ks], &wv[ks * 16 + n * 2]);

        // ---- epilogue: relu + dot W2, quad reduce, store ----
        float s0 = 0.f, s1 = 0.f;
        #pragma unroll
        for (int n = 0; n < 8; ++n) {
            float2 w = *(const float2*)(W2s + n * 8 + (l & 3) * 2);
            s0 = fmaf(fmaxf(acc[n][0], 0.f), w.x, s0);
            s0 = fmaf(fmaxf(acc[n][1], 0.f), w.y, s0);
            s1 = fmaf(fmaxf(acc[n][2], 0.f), w.x, s1);
            s1 = fmaf(fmaxf(acc[n][3], 0.f), w.y, s1);
        }
        s0 += __shfl_xor_sync(0xffffffffu, s0, 1);
        s0 += __shfl_xor_sync(0xffffffffu, s0, 2);
        s1 += __shfl_xor_sync(0xffffffffu, s1, 1);
        s1 += __shfl_xor_sync(0xffffffffu, s1, 2);
        if ((l & 3) == 0) {
            int grow = row0 + t * 128 + wid * 16 + (l >> 2);
            out[(size_t)grow * 64 + i]       = s0;
            out[(size_t)(grow + 8) * 64 + i] = s1;
        }
    }
}

extern "C" void kernel_launch(void* const* d_in, const int* in_sizes, int n_in,
                              void* d_out, int out_size) {
    const float* X   = (const float*)d_in[0];  // [16384, 64]
    const float* Adj = (const float*)d_in[1];  // [64, 64]
    const float* W1  = (const float*)d_in[2];  // [64, 64, 64] (i,h,d)
    const float* W2  = (const float*)d_in[3];  // [64, 64]
    float* out = (float*)d_out;                // [16384, 64]

    prep_kernel<<<640, NT>>>(X, Adj, W1);

    dim3 grid(64, 16384 / (128 * TPB));
    tp_kernel<<<grid, NT>>>(W2, out);
}